// round 17
// baseline (speedup 1.0000x reference)
#include <cuda_runtime.h>
#include <cstdint>

// NolinerSEM: per-expert MLP. out[b,e] = leaky(dot(leaky(W1[e]@x[b,e,:]+b1[e]), W2[e]) + b2[e])
// B=32768, E=90, H=32.
//
// R16: A-operand goes gmem -> registers directly (__ldcs float2 per fragment
// pair), eliminating BOTH the X smem fill (24.6 KB/tile) and the A-fragment
// LDS (49 KB/tile, 2x redundant). L1 traffic/tile 122 -> ~74 KB; the R15
// profile showed L1=78.5% as the binding ceiling. cp.async, X double buffers
// and the odd-e shift are gone; smem is 14 KB static (W1 + biases + partials).
// kstep 11: only t==0 loads (cols 88,89); t>0 fragments are zero (cols 90..95
// are dead via the zero W1 pad) -> no OOB reads anywhere.
// Kept: e-fast grid order, 4m x 2n warp layout, tf32 rna on both operands.

namespace {
constexpr int Ee  = 90;
constexpr int Hh  = 32;
constexpr int STR = 104;   // W1 smem row stride (floats); LDS.64 conflict-free
constexpr int MT  = 64;    // rows per tile
constexpr int T   = 8;     // tiles per CTA
constexpr int KSTEPS = 12; // K padded 90 -> 96
constexpr int THREADS = 256;
constexpr float NEG = 0.33f;
}

__device__ __forceinline__ uint32_t f2tf32(float x) {
    uint32_t u;
    asm("cvt.rna.tf32.f32 %0, %1;" : "=r"(u) : "f"(x));
    return u;
}

__device__ __forceinline__ float lk(float v) { return v >= 0.f ? v : NEG * v; }

__device__ __forceinline__ void mma8(float c[4], const uint32_t a[4], uint32_t b0, uint32_t b1) {
    asm volatile(
        "mma.sync.aligned.m16n8k8.row.col.f32.tf32.tf32.f32 "
        "{%0,%1,%2,%3}, {%4,%5,%6,%7}, {%8,%9}, {%0,%1,%2,%3};"
        : "+f"(c[0]), "+f"(c[1]), "+f"(c[2]), "+f"(c[3])
        : "f"(__uint_as_float(a[0])) /* dummy to keep asm form */, "r"(a[1]), "r"(a[2]), "r"(a[3]), "r"(b0), "r"(b1));
}

// NOTE: the dummy-constraint variant above is wrong; use the real one below.
__device__ __forceinline__ void mma8r(float c[4], uint32_t a0, uint32_t a1, uint32_t a2, uint32_t a3,
                                      uint32_t b0, uint32_t b1) {
    asm volatile(
        "mma.sync.aligned.m16n8k8.row.col.f32.tf32.tf32.f32 "
        "{%0,%1,%2,%3}, {%4,%5,%6,%7}, {%8,%9}, {%0,%1,%2,%3};"
        : "+f"(c[0]), "+f"(c[1]), "+f"(c[2]), "+f"(c[3])
        : "r"(a0), "r"(a1), "r"(a2), "r"(a3), "r"(b0), "r"(b1));
}

__global__ void __launch_bounds__(THREADS, 3) sem_kernel(
    const float* __restrict__ x, const float* __restrict__ W1,
    const float* __restrict__ b1, const float* __restrict__ W2,
    const float* __restrict__ b2, float* __restrict__ out)
{
    __shared__ float Ws[Hh * STR];      // W1[e] tf32 bits, natural [n][k], pad 90..95 = 0
    __shared__ float b1s[Hh];
    __shared__ float w2s[Hh];
    __shared__ float part[2][MT];       // layer-2 partials (n-half 1), ping-pong per tile

    const int e    = blockIdx.x % Ee;       // e-fast: out-line writers co-resident
    const int grp  = blockIdx.x / Ee;
    const int row0 = grp * (MT * T);
    const int tid  = threadIdx.x;
    const int lane = tid & 31;
    const int w    = tid >> 5;

    // ---- prologue: stage W1[e] as tf32 [n][k] (pad 90..95 = 0); biases ----
    {
        const float* wRow = W1 + (size_t)e * (Hh * Ee) + w * Ee;
        uint32_t* wsRow = (uint32_t*)(Ws + w * STR);
        #pragma unroll
        for (int j = 0; j < 4; ++j) {      // rows n = w, w+8, w+16, w+24
            float2 v = *(const float2*)(wRow + lane * 2);
            ((uint2*)wsRow)[lane] = make_uint2(f2tf32(v.x), f2tf32(v.y));
            if (lane < 13) {
                float2 v2 = *(const float2*)(wRow + 64 + lane * 2);
                *(uint2*)(wsRow + 64 + lane * 2) = make_uint2(f2tf32(v2.x), f2tf32(v2.y));
            } else if (lane < 16) {
                *(uint2*)(wsRow + 64 + lane * 2) = make_uint2(0u, 0u);   // k 90..95 = 0
            }
            wRow  += 8 * Ee;
            wsRow += 8 * STR;
        }
    }
    if (tid < Hh) {
        b1s[tid] = b1[e * Hh + tid];
        w2s[tid] = W2[e * Hh + tid];
    }
    __syncthreads();
    const float bias2 = b2[e];

    // ---- warp roles: wm = m-tile (16 rows), wn = n-half (16 cols) ----
    const int g = lane >> 2, t = lane & 3;
    const int wm = w & 3, wn = w >> 2;
    const uint32_t* bBase = (const uint32_t*)Ws + (wn * 16 + g) * STR + 2 * t;

    // ---- tile loop: A fragments straight from gmem (streaming) ----
    #pragma unroll 1
    for (int i = 0; i < T; ++i) {
        // this thread's two A rows for this tile
        const float* xr = x + (size_t)(row0 + i * MT + wm * 16 + g) * (Ee * Ee) + e * Ee;
        const float2* p0 = (const float2*)xr + t;                 // row g,   cols 8ks+2t..+1
        const float2* p1 = (const float2*)(xr + 8 * (Ee * Ee)) + t; // row g+8

        float2 A0[KSTEPS], A1[KSTEPS];
        #pragma unroll
        for (int ks = 0; ks < 11; ++ks) {          // cols <= 89 for all t
            A0[ks] = __ldcs(p0 + 4 * ks);
            A1[ks] = __ldcs(p1 + 4 * ks);
        }
        if (t == 0) {                               // ks=11: cols 88,89 (real) only at t==0
            A0[11] = __ldcs(p0 + 44);
            A1[11] = __ldcs(p1 + 44);
        } else {                                    // cols 90..95 dead (W1 pad = 0)
            A0[11] = make_float2(0.f, 0.f);
            A1[11] = make_float2(0.f, 0.f);
        }

        float c[2][4];
        #pragma unroll
        for (int nl = 0; nl < 2; ++nl)
            #pragma unroll
            for (int j = 0; j < 4; ++j) c[nl][j] = 0.f;

        #pragma unroll
        for (int ks = 0; ks < KSTEPS; ++ks) {
            const uint32_t a0 = f2tf32(A0[ks].x);   // slot k=t   <- col 8ks+2t
            const uint32_t a1 = f2tf32(A1[ks].x);
            const uint32_t a2 = f2tf32(A0[ks].y);   // slot k=t+4 <- col 8ks+2t+1
            const uint32_t a3 = f2tf32(A1[ks].y);
            #pragma unroll
            for (int nl = 0; nl < 2; ++nl) {
                uint2 B = *(const uint2*)(bBase + nl * 8 * STR + ks * 8);
                mma8r(c[nl], a0, a1, a2, a3, B.x, B.y);
            }
        }

        // -- epilogue: leaky(c+b1) . w2 over this warp's 16 cols -> quad reduce --
        float p0s = 0.f, p1s = 0.f;      // rows g, g+8
        #pragma unroll
        for (int nl = 0; nl < 2; ++nl) {
            const int c0 = (wn * 2 + nl) * 8 + 2 * t;
            const float bb0 = b1s[c0], bb1 = b1s[c0 + 1];
            const float ww0 = w2s[c0], ww1 = w2s[c0 + 1];
            p0s += lk(c[nl][0] + bb0) * ww0 + lk(c[nl][1] + bb1) * ww1;
            p1s += lk(c[nl][2] + bb0) * ww0 + lk(c[nl][3] + bb1) * ww1;
        }
        p0s += __shfl_xor_sync(0xffffffffu, p0s, 1);
        p0s += __shfl_xor_sync(0xffffffffu, p0s, 2);
        p1s += __shfl_xor_sync(0xffffffffu, p1s, 1);
        p1s += __shfl_xor_sync(0xffffffffu, p1s, 2);

        if (t == 0 && wn == 1) {
            part[i & 1][wm * 16 + g]     = p0s;
            part[i & 1][wm * 16 + 8 + g] = p1s;
        }
        __syncthreads();   // partials visible; ping-pong buffer makes 1 sync/tile safe
        if (t == 0 && wn == 0) {
            const int r = row0 + i * MT + wm * 16 + g;
            out[(size_t)r * Ee + e]       = lk(p0s + part[i & 1][wm * 16 + g]     + bias2);
            out[(size_t)(r + 8) * Ee + e] = lk(p1s + part[i & 1][wm * 16 + 8 + g] + bias2);
        }
    }
}

extern "C" void kernel_launch(void* const* d_in, const int* in_sizes, int n_in,
                              void* d_out, int out_size) {
    const float* x  = (const float*)d_in[0];
    const float* W1 = (const float*)d_in[1];
    const float* b1 = (const float*)d_in[2];
    const float* W2 = (const float*)d_in[3];
    const float* b2 = (const float*)d_in[4];
    float* out = (float*)d_out;

    const int B = in_sizes[0] / (Ee * Ee);           // 32768
    const int grid = Ee * (B / (MT * T));            // 90 * 64 = 5760 CTAs
    sem_kernel<<<grid, THREADS>>>(x, W1, b1, W2, b2, out);
}